// round 1
// baseline (speedup 1.0000x reference)
#include <cuda_runtime.h>

// ChamferDistance on GB300.
// Inputs (metadata order): xyz1 [B,N,3] f32, xyz2 [B,M,3] f32, B=8, N=M=8192.
// Output: dist1 [B*N] then dist2 [B*M], squared L2 to nearest point in the
// other set, same ||x||^2+||y||^2-2x.y expansion as the reference.

#define CD_THREADS 256
#define CD_P       4      // query points per thread
#define CD_TILE    256    // reference points staged in smem per step

__global__ __launch_bounds__(CD_THREADS, 1)
void chamfer_min_kernel(const float* __restrict__ xyz1,
                        const float* __restrict__ xyz2,
                        float* __restrict__ out,
                        int N, int M, int B)
{
    const int dir = blockIdx.z;                 // 0: q=xyz1 vs r=xyz2 ; 1: swapped
    const int b   = blockIdx.y;

    const float* __restrict__ q = (dir == 0) ? xyz1 : xyz2;
    const float* __restrict__ r = (dir == 0) ? xyz2 : xyz1;
    const int Nq = (dir == 0) ? N : M;
    const int Nr = (dir == 0) ? M : N;
    // dist1 occupies out[0 .. B*N), dist2 occupies out[B*N .. B*N+B*M)
    float* __restrict__ o = out + ((dir == 0) ? 0 : (size_t)B * N);

    const float* __restrict__ qb = q + (size_t)b * Nq * 3;
    const float* __restrict__ rb = r + (size_t)b * Nr * 3;

    const int tid = threadIdx.x;

    // Per-thread query registers (strided rows for coalesced epilogue stores)
    float qx[CD_P], qy[CD_P], qz[CD_P], sq1[CD_P], m[CD_P];
    int   row[CD_P];
    #pragma unroll
    for (int p = 0; p < CD_P; p++) {
        int rw = blockIdx.x * (CD_THREADS * CD_P) + p * CD_THREADS + tid;
        row[p] = rw;
        bool ok = rw < Nq;
        int rr = ok ? rw : 0;
        float x = qb[(size_t)rr * 3 + 0];
        float y = qb[(size_t)rr * 3 + 1];
        float z = qb[(size_t)rr * 3 + 2];
        qx[p] = x; qy[p] = y; qz[p] = z;
        sq1[p] = fmaf(x, x, fmaf(y, y, z * z));
        m[p] = 3.402823466e+38f;   // +FLT_MAX
    }

    __shared__ float4 tile[CD_TILE];

    for (int base = 0; base < Nr; base += CD_TILE) {
        // Stage CD_TILE reference points + their squared norms
        {
            int j = base + tid;          // CD_TILE == CD_THREADS: one point/thread
            float x = 0.f, y = 0.f, z = 0.f, s = 3.402823466e+38f;
            if (j < Nr) {
                x = rb[(size_t)j * 3 + 0];
                y = rb[(size_t)j * 3 + 1];
                z = rb[(size_t)j * 3 + 2];
                s = fmaf(x, x, fmaf(y, y, z * z));  // out-of-range -> +inf-ish sq2
            }
            tile[tid] = make_float4(x, y, z, s);
        }
        __syncthreads();

        // min_j ( sq2_j - 2 * <x, y_j> )  -- sq1 added once at the end
        #pragma unroll 8
        for (int jj = 0; jj < CD_TILE; jj++) {
            float4 p = tile[jj];          // broadcast read, conflict-free
            #pragma unroll
            for (int k = 0; k < CD_P; k++) {
                float t = qx[k] * p.x;
                t = fmaf(qy[k], p.y, t);
                t = fmaf(qz[k], p.z, t);
                float d = fmaf(-2.0f, t, p.w);
                m[k] = fminf(m[k], d);
            }
        }
        __syncthreads();
    }

    #pragma unroll
    for (int p = 0; p < CD_P; p++) {
        if (row[p] < Nq) {
            float d = m[p] + sq1[p];
            o[(size_t)b * Nq + row[p]] = fmaxf(d, 0.0f);
        }
    }
}

extern "C" void kernel_launch(void* const* d_in, const int* in_sizes, int n_in,
                              void* d_out, int out_size)
{
    const float* xyz1 = (const float*)d_in[0];
    const float* xyz2 = (const float*)d_in[1];
    float* out = (float*)d_out;

    const int B = 8;
    const int N = (in_sizes[0] / 3) / B;   // 8192
    const int M = (in_sizes[1] / 3) / B;   // 8192

    int rows_per_block = CD_THREADS * CD_P;           // 1024
    int gx = (N + rows_per_block - 1) / rows_per_block; // 8 (N==M here)

    dim3 grid(gx, B, 2);
    dim3 block(CD_THREADS);
    chamfer_min_kernel<<<grid, block>>>(xyz1, xyz2, out, N, M, B);
}